// round 7
// baseline (speedup 1.0000x reference)
#include <cuda_runtime.h>
#include <cuda_fp16.h>
#include <cstdint>
#include <cstddef>

#define DIM   64
#define CBK   4096
#define MAXM  32768
#define KU    128            // [h1|h2] / [e1|e2] fp16 slices
#define BM    128
#define TAU   0.15f
#define CAP   16384

// ---------------------------------------------------------------------------
// Device scratch (static)
// ---------------------------------------------------------------------------
__device__ float g_nhn[CBK];                                   // -0.5*||e||^2
__device__ __align__(256) __half g_xs[(size_t)MAXM * KU];
__device__ __align__(256) __half g_es[(size_t)CBK * KU];
__device__ int g_cnt;
__device__ int g_flag[CAP];
__device__ __align__(256) __half g_cx[(size_t)CAP * KU];       // compacted flagged rows
__device__ unsigned long long g_best[CAP];

// ---------------------------------------------------------------------------
// PTX helpers (base sm_103 features only)
// ---------------------------------------------------------------------------
__device__ __forceinline__ uint32_t smem_u32(const void* p) {
    uint32_t a;
    asm("{ .reg .u64 t; cvta.to.shared.u64 t, %1; cvt.u32.u64 %0, t; }"
        : "=r"(a) : "l"(p));
    return a;
}
__device__ __forceinline__ void cp16(uint32_t dst, const void* src) {
    asm volatile("cp.async.cg.shared.global [%0], [%1], 16;" :: "r"(dst), "l"(src));
}
__device__ __forceinline__ void cp_commit() {
    asm volatile("cp.async.commit_group;");
}
#define CP_WAIT(n) asm volatile("cp.async.wait_group %0;" :: "n"(n) : "memory")
__device__ __forceinline__ void ldsm4(uint32_t* r, uint32_t addr) {
    asm volatile("ldmatrix.sync.aligned.m8n8.x4.shared.b16 {%0,%1,%2,%3}, [%4];"
                 : "=r"(r[0]), "=r"(r[1]), "=r"(r[2]), "=r"(r[3]) : "r"(addr));
}
__device__ __forceinline__ void ldsm2(uint32_t* r, uint32_t addr) {
    asm volatile("ldmatrix.sync.aligned.m8n8.x2.shared.b16 {%0,%1}, [%2];"
                 : "=r"(r[0]), "=r"(r[1]) : "r"(addr));
}
__device__ __forceinline__ void hmma(float* d, const uint32_t* a, const uint32_t* b) {
    asm volatile("mma.sync.aligned.m16n8k16.row.col.f32.f16.f16.f32 "
                 "{%0,%1,%2,%3}, {%4,%5,%6,%7}, {%8,%9}, {%0,%1,%2,%3};"
                 : "+f"(d[0]), "+f"(d[1]), "+f"(d[2]), "+f"(d[3])
                 : "r"(a[0]), "r"(a[1]), "r"(a[2]), "r"(a[3]),
                   "r"(b[0]), "r"(b[1]));
}
__device__ __forceinline__ uint32_t fkey(float f) {   // orderable float bits
    uint32_t u = __float_as_uint(f);
    return (u & 0x80000000u) ? ~u : (u | 0x80000000u);
}

// ---------------------------------------------------------------------------
// Split fp32 -> (h1,h2) fp16.  Exact 3-term score: h1e1 + h1e2 + h2e1.
// ---------------------------------------------------------------------------
__device__ __forceinline__ void split8(float4 lo, float4 hi, uint4* h) {
    float v[8] = {lo.x, lo.y, lo.z, lo.w, hi.x, hi.y, hi.z, hi.w};
    union U { unsigned short s[8]; uint4 u; } u1, u2;
#pragma unroll
    for (int k = 0; k < 8; k++) {
        float a = v[k];
        __half b1 = __float2half_rn(a);
        float r1 = a - __half2float(b1);
        __half b2 = __float2half_rn(r1);
        u1.s[k] = *reinterpret_cast<unsigned short*>(&b1);
        u2.s[k] = *reinterpret_cast<unsigned short*>(&b2);
    }
    h[0] = u1.u; h[1] = u2.u;
}

__global__ void split_kernel(const float* __restrict__ x,
                             const float* __restrict__ e, int M) {
    const int gid = blockIdx.x * blockDim.x + threadIdx.x;
    if (gid < M * 8) {
        int row = gid >> 3, c8 = gid & 7;
        const float4* p = reinterpret_cast<const float4*>(x + (size_t)row * DIM + c8 * 8);
        uint4 h[2];
        split8(p[0], p[1], h);
        __half* dst = g_xs + (size_t)row * KU + c8 * 8;
        *reinterpret_cast<uint4*>(dst)       = h[0];
        *reinterpret_cast<uint4*>(dst + DIM) = h[1];
    }
    if (gid < CBK * 8) {
        int row = gid >> 3, c8 = gid & 7;
        const float4* p = reinterpret_cast<const float4*>(e + (size_t)row * DIM + c8 * 8);
        uint4 h[2];
        split8(p[0], p[1], h);
        __half* dst = g_es + (size_t)row * KU + c8 * 8;
        *reinterpret_cast<uint4*>(dst)       = h[0];
        *reinterpret_cast<uint4*>(dst + DIM) = h[1];
    }
}

// -0.5*||e||^2 + counter reset
__global__ void hn_kernel(const float* __restrict__ e) {
    int tid = blockIdx.x * blockDim.x + threadIdx.x;
    if (tid == 0) g_cnt = 0;
    if (tid < CBK * 4) {
        int row = tid >> 2, p = tid & 3;
        const float4* v = reinterpret_cast<const float4*>(e + (size_t)row * DIM) + p * 4;
        float s = 0.f;
#pragma unroll
        for (int i = 0; i < 4; i++) {
            float4 q = v[i];
            s += q.x * q.x + q.y * q.y + q.z * q.z + q.w * q.w;
        }
        s += __shfl_xor_sync(0xffffffffu, s, 1);
        s += __shfl_xor_sync(0xffffffffu, s, 2);
        if (p == 0) g_nhn[row] = -0.5f * s;
    }
}

// ---------------------------------------------------------------------------
// Shared GEMM micro-kernel
// ---------------------------------------------------------------------------
template<int TERMS>
__device__ __forceinline__ void compute_stage(
    float (&acc)[4][4][4], const uint32_t* aBase, uint32_t amask, uint32_t asel,
    uint32_t bst, const uint32_t* bOff, uint32_t bmask, uint32_t bsel)
{
#pragma unroll
    for (int ks = 0; ks < 4; ks++) {
        uint32_t b[4][2];
        const uint32_t boff = (((uint32_t)(ks * 2) + bsel) << 4) ^ bmask;
#pragma unroll
        for (int ni = 0; ni < 4; ni++) ldsm2(b[ni], bst + bOff[ni] + boff);
        const uint32_t aoff = (((uint32_t)(ks * 2) + asel) << 4) ^ amask;
#pragma unroll
        for (int t = 0; t < TERMS; t++) {
            uint32_t a[4][4];
#pragma unroll
            for (int mi = 0; mi < 4; mi++)
                ldsm4(a[mi], aBase[mi] + t * 16384 + aoff);
#pragma unroll
            for (int mi = 0; mi < 4; mi++)
#pragma unroll
                for (int ni = 0; ni < 4; ni++)
                    hmma(acc[mi][ni], a[mi], b[ni]);
        }
    }
}

// ---------------------------------------------------------------------------
// Pass 1: single-term fp16 GEMM, per-row top-2, margin test, provisional write.
// SMEM: A 16KB resident (h1), B ring 4x16KB.
// ---------------------------------------------------------------------------
#define P1_SMEM (16384 + 65536)

__global__ __launch_bounds__(256, 2)
void vq_pass1(const float* __restrict__ embed,
              float* __restrict__ outq,
              float* __restrict__ out_ind) {
    extern __shared__ __align__(128) char smem[];
    const uint32_t As_u = smem_u32(smem);
    const uint32_t Bs_u = As_u + 16384;

    const int tid  = threadIdx.x;
    const int lane = tid & 31, wid = tid >> 5;
    const int wm = wid & 1, wn = wid >> 1;
    const int g = lane >> 2, tig = lane & 3;
    const int mtile = blockIdx.x;

    auto prefetchB = [&](int nt, int slot) {
        const __half* src = g_es + (size_t)nt * BM * KU;   // slice e1
        const uint32_t dbase = Bs_u + slot * 16384;
#pragma unroll
        for (int i = 0; i < 4; i++) {
            int idx = tid + i * 256;
            int row = idx >> 3, c = idx & 7;
            cp16(dbase + row * 128 + ((c ^ (row & 7)) << 4),
                 src + (size_t)row * KU + c * 8);
        }
    };

    {   // A (h1 slice) + first 3 B stages
        const __half* xa = g_xs + (size_t)mtile * BM * KU;
#pragma unroll
        for (int i = 0; i < 4; i++) {
            int idx = tid + i * 256;
            int row = idx >> 3, c = idx & 7;
            cp16(As_u + row * 128 + ((c ^ (row & 7)) << 4),
                 xa + (size_t)row * KU + c * 8);
        }
        prefetchB(0, 0); cp_commit();
        prefetchB(1, 1); cp_commit();
        prefetchB(2, 2); cp_commit();
    }

    uint32_t aBase[4];
#pragma unroll
    for (int mi = 0; mi < 4; mi++)
        aBase[mi] = As_u + (wm * 64 + mi * 16 + (lane & 15)) * 128;
    const uint32_t amask = (lane & 7) << 4;
    const uint32_t asel  = lane >> 4;
    uint32_t bOff[4];
#pragma unroll
    for (int ni = 0; ni < 4; ni++)
        bOff[ni] = (wn * 32 + ni * 8 + (lane & 7)) * 128;
    const uint32_t bmask = (lane & 7) << 4;
    const uint32_t bsel  = (lane >> 3) & 1;

    float b1[8], b2[8];
    int   i1[8];
#pragma unroll
    for (int s = 0; s < 8; s++) { b1[s] = -3.402823466e38f; b2[s] = -3.402823466e38f; i1[s] = 0; }

    float acc[4][4][4];
    for (int si = 0; si < 32; si++) {
        CP_WAIT(2);
        __syncthreads();
        if (si < 29) prefetchB(si + 3, (si + 3) & 3);
        cp_commit();

#pragma unroll
        for (int mi = 0; mi < 4; mi++)
#pragma unroll
            for (int ni = 0; ni < 4; ni++)
#pragma unroll
                for (int r = 0; r < 4; r++) acc[mi][ni][r] = 0.f;

        compute_stage<1>(acc, aBase, amask, asel, Bs_u + (si & 3) * 16384,
                         bOff, bmask, bsel);

        const int colb = si * 128 + wn * 32 + tig * 2;
#pragma unroll
        for (int ni = 0; ni < 4; ni++) {
            const int c0 = colb + ni * 8;
            float2 nh = *reinterpret_cast<const float2*>(&g_nhn[c0]);
#pragma unroll
            for (int mi = 0; mi < 4; mi++) {
                float s0 = acc[mi][ni][0] + nh.x;
                float s1 = acc[mi][ni][1] + nh.y;
                float s2 = acc[mi][ni][2] + nh.x;
                float s3 = acc[mi][ni][3] + nh.y;
                const int lo = mi * 2, hi = mi * 2 + 1;
                if (s0 > b1[lo]) { b2[lo] = b1[lo]; b1[lo] = s0; i1[lo] = c0; }
                else if (s0 > b2[lo]) b2[lo] = s0;
                if (s1 > b1[lo]) { b2[lo] = b1[lo]; b1[lo] = s1; i1[lo] = c0 + 1; }
                else if (s1 > b2[lo]) b2[lo] = s1;
                if (s2 > b1[hi]) { b2[hi] = b1[hi]; b1[hi] = s2; i1[hi] = c0; }
                else if (s2 > b2[hi]) b2[hi] = s2;
                if (s3 > b1[hi]) { b2[hi] = b1[hi]; b1[hi] = s3; i1[hi] = c0 + 1; }
                else if (s3 > b2[hi]) b2[hi] = s3;
            }
        }
    }

    // quad reduce (top-2 merge over disjoint candidate sets)
#pragma unroll
    for (int s = 0; s < 8; s++) {
#pragma unroll
        for (int d = 1; d < 4; d <<= 1) {
            float ov1 = __shfl_xor_sync(0xffffffffu, b1[s], d);
            int   oi1 = __shfl_xor_sync(0xffffffffu, i1[s], d);
            float ov2 = __shfl_xor_sync(0xffffffffu, b2[s], d);
            if (ov1 > b1[s] || (ov1 == b1[s] && oi1 < i1[s])) {
                b2[s] = fmaxf(b1[s], ov2); b1[s] = ov1; i1[s] = oi1;
            } else {
                b2[s] = fmaxf(b2[s], ov1);
            }
        }
    }
    __syncthreads();
    float* rv1 = reinterpret_cast<float*>(smem + 16384);
    int*   ri1 = reinterpret_cast<int*>(smem + 16384 + 2048);
    float* rv2 = reinterpret_cast<float*>(smem + 16384 + 4096);
    if (tig == 0) {
#pragma unroll
        for (int s = 0; s < 8; s++) {
            int row = wm * 64 + (s >> 1) * 16 + g + (s & 1) * 8;
            rv1[row * 4 + wn] = b1[s];
            ri1[row * 4 + wn] = i1[s];
            rv2[row * 4 + wn] = b2[s];
        }
    }
    __syncthreads();

    if (tid < BM) {
        float B1 = rv1[tid * 4], B2 = rv2[tid * 4];
        int   I1 = ri1[tid * 4];
#pragma unroll
        for (int j = 1; j < 4; j++) {
            float a1 = rv1[tid * 4 + j], a2 = rv2[tid * 4 + j];
            int   ai = ri1[tid * 4 + j];
            if (a1 > B1 || (a1 == B1 && ai < I1)) {
                B2 = fmaxf(B1, a2); B1 = a1; I1 = ai;
            } else {
                B2 = fmaxf(B2, a1);
            }
        }
        const int grow = mtile * BM + tid;
        if (out_ind) out_ind[grow] = (float)I1;
        const float4* e4 = reinterpret_cast<const float4*>(embed + (size_t)I1 * DIM);
        float4* o4 = reinterpret_cast<float4*>(outq + (size_t)grow * DIM);
#pragma unroll
        for (int i = 0; i < DIM / 4; i++) o4[i] = e4[i];
        if (B1 - B2 < TAU) {
            int pos = atomicAdd(&g_cnt, 1);
            if (pos < CAP) { g_flag[pos] = grow; g_best[pos] = 0ULL; }
        }
    }
}

// ---------------------------------------------------------------------------
// Compact flagged rows' (h1,h2) into g_cx
// ---------------------------------------------------------------------------
__global__ void compact_kernel() {
    int n = g_cnt; if (n > CAP) n = CAP;
    for (int i = blockIdx.x * blockDim.x + threadIdx.x; i < n;
         i += gridDim.x * blockDim.x) {
        int row = g_flag[i];
        const uint4* s = reinterpret_cast<const uint4*>(g_xs + (size_t)row * KU);
        uint4* d = reinterpret_cast<uint4*>(g_cx + (size_t)i * KU);
#pragma unroll
        for (int j = 0; j < 16; j++) d[j] = s[j];
    }
}

// ---------------------------------------------------------------------------
// Rescore: exact 3-term GEMM over flagged rows, split over 8 codebook chunks.
// grid (8, 32): x = 512-code chunk, y = m-tile (strided).
// SMEM: A 2x16KB (h1,h2) + B ring 4x16KB = 96KB.
// ---------------------------------------------------------------------------
#define RS_SMEM (32768 + 65536)

__global__ __launch_bounds__(256, 2)
void vq_rescore() {
    int cnt = g_cnt; if (cnt > CAP) cnt = CAP;
    extern __shared__ __align__(128) char smem[];
    const uint32_t As_u = smem_u32(smem);
    const uint32_t Bs_u = As_u + 32768;

    const int tid  = threadIdx.x;
    const int lane = tid & 31, wid = tid >> 5;
    const int wm = wid & 1, wn = wid >> 1;
    const int g = lane >> 2, tig = lane & 3;
    const int nchunk = blockIdx.x;     // 0..7

    uint32_t aBase[4];
#pragma unroll
    for (int mi = 0; mi < 4; mi++)
        aBase[mi] = As_u + (wm * 64 + mi * 16 + (lane & 15)) * 128;
    const uint32_t amask = (lane & 7) << 4;
    const uint32_t asel  = lane >> 4;
    uint32_t bOff[4];
#pragma unroll
    for (int ni = 0; ni < 4; ni++)
        bOff[ni] = (wn * 32 + ni * 8 + (lane & 7)) * 128;
    const uint32_t bmask = (lane & 7) << 4;
    const uint32_t bsel  = (lane >> 3) & 1;

    auto prefetchB = [&](int st, int slot) {   // st = 0..7 : (nt_local, slice)
        const int nt = nchunk * 4 + (st >> 1), s = st & 1;
        const __half* src = g_es + (size_t)nt * BM * KU + s * DIM;
        const uint32_t dbase = Bs_u + slot * 16384;
#pragma unroll
        for (int i = 0; i < 4; i++) {
            int idx = tid + i * 256;
            int row = idx >> 3, c = idx & 7;
            cp16(dbase + row * 128 + ((c ^ (row & 7)) << 4),
                 src + (size_t)row * KU + c * 8);
        }
    };

    for (int mt = blockIdx.y; mt * BM < cnt; mt += gridDim.y) {
        // A: compact rows (2 slices)
#pragma unroll
        for (int s = 0; s < 2; s++)
#pragma unroll
            for (int i = 0; i < 4; i++) {
                int idx = tid + i * 256;
                int row = idx >> 3, c = idx & 7;
                int ci = mt * BM + row; if (ci >= cnt) ci = cnt - 1;
                cp16(As_u + s * 16384 + row * 128 + ((c ^ (row & 7)) << 4),
                     g_cx + (size_t)ci * KU + s * DIM + c * 8);
            }
        prefetchB(0, 0); cp_commit();
        prefetchB(1, 1); cp_commit();
        prefetchB(2, 2); cp_commit();

        float best = -3.402823466e38f;
        int   bi = 0;
        float acc[4][4][4];

        for (int si = 0; si < 8; si++) {
            const int cs = si & 1, ntl = si >> 1;
            CP_WAIT(2);
            __syncthreads();
            if (si < 5) prefetchB(si + 3, (si + 3) & 3);
            cp_commit();

            if (cs == 0) {
#pragma unroll
                for (int mi = 0; mi < 4; mi++)
#pragma unroll
                    for (int ni = 0; ni < 4; ni++)
#pragma unroll
                        for (int r = 0; r < 4; r++) acc[mi][ni][r] = 0.f;
            }
            const uint32_t bst = Bs_u + (si & 3) * 16384;
            if (cs == 0) compute_stage<2>(acc, aBase, amask, asel, bst, bOff, bmask, bsel);
            else         compute_stage<1>(acc, aBase, amask, asel, bst, bOff, bmask, bsel);

            if (cs == 1) {
                const int colb = (nchunk * 4 + ntl) * 128 + wn * 32 + tig * 2;
#pragma unroll
                for (int ni = 0; ni < 4; ni++) {
                    const int c0 = colb + ni * 8;
                    float2 nh = *reinterpret_cast<const float2*>(&g_nhn[c0]);
#pragma unroll
                    for (int mi = 0; mi < 4; mi++) {
                        float s0 = acc[mi][ni][0] + nh.x;
                        float s1 = acc[mi][ni][1] + nh.y;
                        float s2 = acc[mi][ni][2] + nh.x;
                        float s3 = acc[mi][ni][3] + nh.y;
                        // per-thread slot scores map to 2 rows; fold rows via
                        // packing row parity into separate reduce below.
                        // slot lo = row (wm*64 + mi*16 + g), hi = +8
                        // track per-slot best in local arrays:
                        (void)s0; (void)s1; (void)s2; (void)s3;
                        // handled just after (see bestv array)
                        // -- replaced by explicit code below --
                    }
                }
                // explicit per-slot tracking (8 slots like pass1, single best)
                {
#pragma unroll
                    for (int ni = 0; ni < 4; ni++) {
                        const int c0 = colb + ni * 8;
                        float2 nh = *reinterpret_cast<const float2*>(&g_nhn[c0]);
#pragma unroll
                        for (int mi = 0; mi < 4; mi++) {
                            float s0 = acc[mi][ni][0] + nh.x;
                            float s1 = acc[mi][ni][1] + nh.y;
                            float s2 = acc[mi][ni][2] + nh.x;
                            float s3 = acc[mi][ni][3] + nh.y;
                            // encode slot in high bits of a combined reduce:
                            // simpler: keep one best per thread PER SLOT via
                            // arrays declared outside (bestv/bidxv)
                            extern __shared__ float _dummy[]; (void)_dummy;
                            (void)s0; (void)s1; (void)s2; (void)s3;
                        }
                    }
                }
            }
        }
        // NOTE: the two no-op blocks above are eliminated; real tracking below
        // recomputes fold per cs==1 stage was needed inline. To keep code
        // correct and simple, we redo the loop with tracking arrays:
        // (dead code above compiled out; actual implementation uses bestv[])
        (void)best; (void)bi;

        // ---- real pass with tracking arrays (single clean loop) ----------
        // re-run is avoided: see vq_rescore2 below (this kernel unused)
        break;
    }
}

// ---------------------------------------------------------------------------
// Clean rescore implementation (used).
// ---------------------------------------------------------------------------
__global__ __launch_bounds__(256, 2)
void vq_rescore2() {
    int cnt = g_cnt; if (cnt > CAP) cnt = CAP;
    extern __shared__ __align__(128) char smem[];
    const uint32_t As_u = smem_u32(smem);
    const uint32_t Bs_u = As_u + 32768;

    const int tid  = threadIdx.x;
    const int lane = tid & 31, wid = tid >> 5;
    const int wm = wid & 1, wn = wid >> 1;
    const int g = lane >> 2, tig = lane & 3;
    const int nchunk = blockIdx.x;

    uint32_t aBase[4];
#pragma unroll
    for (int mi = 0; mi < 4; mi++)
        aBase[mi] = As_u + (wm * 64 + mi * 16 + (lane & 15)) * 128;
    const uint32_t amask = (lane & 7) << 4;
    const uint32_t asel  = lane >> 4;
    uint32_t bOff[4];
#pragma unroll
    for (int ni = 0; ni < 4; ni++)
        bOff[ni] = (wn * 32 + ni * 8 + (lane & 7)) * 128;
    const uint32_t bmask = (lane & 7) << 4;
    const uint32_t bsel  = (lane >> 3) & 1;

    auto prefetchB = [&](int st, int slot) {
        const int nt = nchunk * 4 + (st >> 1), s = st & 1;
        const __half* src = g_es + (size_t)nt * BM * KU + s * DIM;
        const uint32_t dbase = Bs_u + slot * 16384;
#pragma unroll
        for (int i = 0; i < 4; i++) {
            int idx = tid + i * 256;
            int row = idx >> 3, c = idx & 7;
            cp16(dbase + row * 128 + ((c ^ (row & 7)) << 4),
                 src + (size_t)row * KU + c * 8);
        }
    };

    for (int mt = blockIdx.y; mt * BM < cnt; mt += gridDim.y) {
#pragma unroll
        for (int s = 0; s < 2; s++)
#pragma unroll
            for (int i = 0; i < 4; i++) {
                int idx = tid + i * 256;
                int row = idx >> 3, c = idx & 7;
                int ci = mt * BM + row; if (ci >= cnt) ci = cnt - 1;
                cp16(As_u + s * 16384 + row * 128 + ((c ^ (row & 7)) << 4),
                     g_cx + (size_t)ci * KU + s * DIM + c * 8);
            }
        prefetchB(0, 0); cp_commit();
        prefetchB(1, 1); cp_commit();
        prefetchB(2, 2); cp_commit();

        float bestv[8]; int bidxv[8];
#pragma unroll
        for (int s = 0; s < 8; s++) { bestv[s] = -3.402823466e38f; bidxv[s] = 0; }
        float acc[4][4][4];

        for (int si = 0; si < 8; si++) {
            const int cs = si & 1, ntl = si >> 1;
            CP_WAIT(2);
            __syncthreads();
            if (si < 5) prefetchB(si + 3, (si + 3) & 3);
            cp_commit();

            if (cs == 0) {
#pragma unroll
                for (int mi = 0; mi < 4; mi++)
#pragma unroll
                    for (int ni = 0; ni < 4; ni++)
#pragma unroll
                        for (int r = 0; r < 4; r++) acc[mi][ni][r] = 0.f;
            }
            const uint32_t bst = Bs_u + (si & 3) * 16384;
            if (cs == 0) compute_stage<2>(acc, aBase, amask, asel, bst, bOff, bmask, bsel);
            else         compute_stage<1>(acc, aBase, amask, asel, bst, bOff, bmask, bsel);

            if (cs == 1) {
                const int colb = (nchunk * 4 + ntl) * 128 + wn * 32 + tig * 2;
#pragma unroll
                for (int ni = 0; ni < 4; ni++) {
                    const int c0 = colb + ni * 8;
                    float2 nh = *reinterpret_cast<const float2*>(&g_nhn[c0]);
#pragma unroll
                    for (int mi = 0; mi < 4; mi++) {
                        float s0 = acc[mi][ni][0] + nh.x;
                        float s1 = acc[mi][ni][1] + nh.y;
                        float s2 = acc[mi][ni][2] + nh.x;
                        float s3 = acc[mi][ni][3] + nh.y;
                        const int lo = mi * 2, hi = mi * 2 + 1;
                        if (s0 > bestv[lo]) { bestv[lo] = s0; bidxv[lo] = c0; }
                        if (s1 > bestv[lo]) { bestv[lo] = s1; bidxv[lo] = c0 + 1; }
                        if (s2 > bestv[hi]) { bestv[hi] = s2; bidxv[hi] = c0; }
                        if (s3 > bestv[hi]) { bestv[hi] = s3; bidxv[hi] = c0 + 1; }
                    }
                }
            }
        }

        // quad + cross-warp reduce (single best, lowest-index ties)
#pragma unroll
        for (int s = 0; s < 8; s++) {
#pragma unroll
            for (int d = 1; d < 4; d <<= 1) {
                float ov = __shfl_xor_sync(0xffffffffu, bestv[s], d);
                int   oi = __shfl_xor_sync(0xffffffffu, bidxv[s], d);
                if (ov > bestv[s] || (ov == bestv[s] && oi < bidxv[s])) {
                    bestv[s] = ov; bidxv[s] = oi;
                }
            }
        }
        __syncthreads();
        float* redv = reinterpret_cast<float*>(smem + 32768);
        int*   redi = reinterpret_cast<int*>(smem + 32768 + 2048);
        if (tig == 0) {
#pragma unroll
            for (int s = 0; s < 8; s++) {
                int row = wm * 64 + (s >> 1) * 16 + g + (s & 1) * 8;
                redv[row * 4 + wn] = bestv[s];
                redi[row * 4 + wn] = bidxv[s];
            }
        }
        __syncthreads();
        if (tid < BM && mt * BM + tid < cnt) {
            float bv = redv[tid * 4];
            int   bi = redi[tid * 4];
#pragma unroll
            for (int j = 1; j < 4; j++) {
                float v  = redv[tid * 4 + j];
                int   ii = redi[tid * 4 + j];
                if (v > bv || (v == bv && ii < bi)) { bv = v; bi = ii; }
            }
            unsigned long long packed =
                ((unsigned long long)fkey(bv) << 32) | (unsigned)(4095 - bi);
            atomicMax(&g_best[mt * BM + tid], packed);
        }
        __syncthreads();   // protect reduce scratch / smem before next tile
    }
}

// ---------------------------------------------------------------------------
// Writeback flagged rows from g_best
// ---------------------------------------------------------------------------
__global__ void writeback_kernel(const float* __restrict__ embed,
                                 float* __restrict__ outq,
                                 float* __restrict__ out_ind) {
    int n = g_cnt; if (n > CAP) n = CAP;
    for (int i = blockIdx.x * blockDim.x + threadIdx.x; i < n;
         i += gridDim.x * blockDim.x) {
        int row = g_flag[i];
        unsigned long long p = g_best[i];
        int idx = 4095 - (int)(p & 0xFFFu);
        if (out_ind) out_ind[row] = (float)idx;
        const float4* e4 = reinterpret_cast<const float4*>(embed + (size_t)idx * DIM);
        float4* o4 = reinterpret_cast<float4*>(outq + (size_t)row * DIM);
#pragma unroll
        for (int j = 0; j < DIM / 4; j++) o4[j] = e4[j];
    }
}

// Defensive tail fill.
__global__ void fill_kernel(float* __restrict__ out, int start, int end) {
    int i = start + blockIdx.x * blockDim.x + threadIdx.x;
    if (i < end) out[i] = 0.f;
}

// ---------------------------------------------------------------------------
extern "C" void kernel_launch(void* const* d_in, const int* in_sizes, int n_in,
                              void* d_out, int out_size) {
    const float* x     = (const float*)d_in[0];
    const float* embed = (const float*)d_in[1];
    float* out = (float*)d_out;

    const int M = in_sizes[0] / DIM;  // 32768

    int nthr = M * 8 > CBK * 8 ? M * 8 : CBK * 8;
    split_kernel<<<(nthr + 255) / 256, 256>>>(x, embed, M);
    hn_kernel<<<(CBK * 4 + 255) / 256, 256>>>(embed);

    cudaFuncSetAttribute(vq_pass1,
                         cudaFuncAttributeMaxDynamicSharedMemorySize, P1_SMEM);
    cudaFuncSetAttribute(vq_rescore2,
                         cudaFuncAttributeMaxDynamicSharedMemorySize, RS_SMEM);

    float* oind = (out_size >= M * DIM + M) ? (out + (size_t)M * DIM) : nullptr;
    vq_pass1<<<M / BM, 256, P1_SMEM>>>(embed, out, oind);
    compact_kernel<<<64, 256>>>();
    vq_rescore2<<<dim3(8, 32), 256, RS_SMEM>>>();
    writeback_kernel<<<32, 256>>>(embed, out, oind);

    int written = M * DIM + (oind ? M : 0);
    if (out_size > written) {
        int tail = out_size - written;
        fill_kernel<<<(tail + 255) / 256, 256>>>(out, written, out_size);
    }
}

// round 8
// speedup vs baseline: 1.3050x; 1.3050x over previous
#include <cuda_runtime.h>
#include <cuda_fp16.h>
#include <cstdint>
#include <cstddef>

#define DIM   64
#define CBK   4096
#define MAXM  32768
#define KU    128            // [h1|h2] fp16 slices per row
#define BM    128
#define TAU   0.15f
#define CAP   16384

// ---------------------------------------------------------------------------
// Device scratch (static)
// ---------------------------------------------------------------------------
__device__ float g_nhn[CBK];                                   // -0.5*||e||^2
__device__ __align__(256) __half g_xs[(size_t)MAXM * KU];      // x: h1|h2
__device__ __align__(256) __half g_es[(size_t)CBK * KU];       // e: h1|h2 (rescore)
__device__ __align__(256) uint2 g_e1f[CBK * DIM / 4];          // e1 in mma-frag order
__device__ int g_cnt;
__device__ int g_flag[CAP];
__device__ __align__(256) __half g_cx[(size_t)CAP * KU];       // compacted flagged rows
__device__ unsigned long long g_best[CAP];

// ---------------------------------------------------------------------------
// PTX helpers (base sm_103 features only)
// ---------------------------------------------------------------------------
__device__ __forceinline__ uint32_t smem_u32(const void* p) {
    uint32_t a;
    asm("{ .reg .u64 t; cvta.to.shared.u64 t, %1; cvt.u32.u64 %0, t; }"
        : "=r"(a) : "l"(p));
    return a;
}
__device__ __forceinline__ void cp16(uint32_t dst, const void* src) {
    asm volatile("cp.async.cg.shared.global [%0], [%1], 16;" :: "r"(dst), "l"(src));
}
__device__ __forceinline__ void cp_commit() {
    asm volatile("cp.async.commit_group;");
}
#define CP_WAIT(n) asm volatile("cp.async.wait_group %0;" :: "n"(n) : "memory")
__device__ __forceinline__ void ldsm4(uint32_t* r, uint32_t addr) {
    asm volatile("ldmatrix.sync.aligned.m8n8.x4.shared.b16 {%0,%1,%2,%3}, [%4];"
                 : "=r"(r[0]), "=r"(r[1]), "=r"(r[2]), "=r"(r[3]) : "r"(addr));
}
__device__ __forceinline__ void ldsm2(uint32_t* r, uint32_t addr) {
    asm volatile("ldmatrix.sync.aligned.m8n8.x2.shared.b16 {%0,%1}, [%2];"
                 : "=r"(r[0]), "=r"(r[1]) : "r"(addr));
}
__device__ __forceinline__ void hmma(float* d, const uint32_t* a, const uint32_t* b) {
    asm volatile("mma.sync.aligned.m16n8k16.row.col.f32.f16.f16.f32 "
                 "{%0,%1,%2,%3}, {%4,%5,%6,%7}, {%8,%9}, {%0,%1,%2,%3};"
                 : "+f"(d[0]), "+f"(d[1]), "+f"(d[2]), "+f"(d[3])
                 : "r"(a[0]), "r"(a[1]), "r"(a[2]), "r"(a[3]),
                   "r"(b[0]), "r"(b[1]));
}
__device__ __forceinline__ uint32_t fkey(float f) {   // orderable float bits
    uint32_t u = __float_as_uint(f);
    return (u & 0x80000000u) ? ~u : (u | 0x80000000u);
}

// ---------------------------------------------------------------------------
// Split fp32 -> (h1,h2) fp16.  Exact 3-term score: h1e1 + h1e2 + h2e1.
// ---------------------------------------------------------------------------
__device__ __forceinline__ void split8(float4 lo, float4 hi, uint4* h) {
    float v[8] = {lo.x, lo.y, lo.z, lo.w, hi.x, hi.y, hi.z, hi.w};
    union U { unsigned short s[8]; uint4 u; } u1, u2;
#pragma unroll
    for (int k = 0; k < 8; k++) {
        float a = v[k];
        __half b1 = __float2half_rn(a);
        float r1 = a - __half2float(b1);
        __half b2 = __float2half_rn(r1);
        u1.s[k] = *reinterpret_cast<unsigned short*>(&b1);
        u2.s[k] = *reinterpret_cast<unsigned short*>(&b2);
    }
    h[0] = u1.u; h[1] = u2.u;
}

__global__ void split_kernel(const float* __restrict__ x,
                             const float* __restrict__ e, int M) {
    const int gid = blockIdx.x * blockDim.x + threadIdx.x;
    if (gid < M * 8) {
        int row = gid >> 3, c8 = gid & 7;
        const float4* p = reinterpret_cast<const float4*>(x + (size_t)row * DIM + c8 * 8);
        uint4 h[2];
        split8(p[0], p[1], h);
        __half* dst = g_xs + (size_t)row * KU + c8 * 8;
        *reinterpret_cast<uint4*>(dst)       = h[0];
        *reinterpret_cast<uint4*>(dst + DIM) = h[1];
    }
    if (gid < CBK * 8) {
        int row = gid >> 3, c8 = gid & 7;
        const float4* p = reinterpret_cast<const float4*>(e + (size_t)row * DIM + c8 * 8);
        uint4 h[2];
        split8(p[0], p[1], h);
        __half* dst = g_es + (size_t)row * KU + c8 * 8;
        *reinterpret_cast<uint4*>(dst)       = h[0];
        *reinterpret_cast<uint4*>(dst + DIM) = h[1];
    }
}

// -0.5*||e||^2 + counter reset
__global__ void hn_kernel(const float* __restrict__ e) {
    int tid = blockIdx.x * blockDim.x + threadIdx.x;
    if (tid == 0) g_cnt = 0;
    if (tid < CBK * 4) {
        int row = tid >> 2, p = tid & 3;
        const float4* v = reinterpret_cast<const float4*>(e + (size_t)row * DIM) + p * 4;
        float s = 0.f;
#pragma unroll
        for (int i = 0; i < 4; i++) {
            float4 q = v[i];
            s += q.x * q.x + q.y * q.y + q.z * q.z + q.w * q.w;
        }
        s += __shfl_xor_sync(0xffffffffu, s, 1);
        s += __shfl_xor_sync(0xffffffffu, s, 2);
        if (p == 0) g_nhn[row] = -0.5f * s;
    }
}

// ---------------------------------------------------------------------------
// Pack e1 = fp16(embed) in m16n8k16 B-fragment order:
// frag index = ((nt*4 + ks)*16 + nf)*32 + lane
//   n = nt*128 + nf*8 + lane/4 ; k0 = ks*16 + (lane%4)*2
//   payload = { (e[n][k0],e[n][k0+1]) , (e[n][k0+8],e[n][k0+9]) }
// ---------------------------------------------------------------------------
__global__ void pack_kernel(const float* __restrict__ e) {
    int gid = blockIdx.x * blockDim.x + threadIdx.x;
    if (gid < CBK * DIM / 4) {
        int lane = gid & 31;
        int nf   = (gid >> 5) & 15;
        int ks   = (gid >> 9) & 3;
        int nt   = gid >> 11;
        int n  = nt * 128 + nf * 8 + (lane >> 2);
        int k0 = ks * 16 + (lane & 3) * 2;
        const float* er = e + (size_t)n * DIM;
        __half2 b0 = __floats2half2_rn(er[k0], er[k0 + 1]);
        __half2 b1 = __floats2half2_rn(er[k0 + 8], er[k0 + 9]);
        uint2 v;
        v.x = *reinterpret_cast<uint32_t*>(&b0);
        v.y = *reinterpret_cast<uint32_t*>(&b1);
        g_e1f[gid] = v;
    }
}

__global__ void init_best_kernel() {
    int i = blockIdx.x * blockDim.x + threadIdx.x;
    if (i < CAP) g_best[i] = 0ULL;
}

// ---------------------------------------------------------------------------
// Pass 1: single-term fp16 GEMM (h1 . e1), B via direct LDG of fragments,
// A resident in SMEM, NO syncthreads in the mainloop. Per-row top-2 margin
// test; flagged rows are compacted inline.
// ---------------------------------------------------------------------------
#define P1_SMEM 16384

__global__ __launch_bounds__(256, 2)
void vq_pass1(const float* __restrict__ embed,
              float* __restrict__ outq,
              float* __restrict__ out_ind) {
    extern __shared__ __align__(128) char smem[];
    const uint32_t As_u = smem_u32(smem);

    const int tid  = threadIdx.x;
    const int lane = tid & 31, wid = tid >> 5;
    const int wm = wid & 1, wn = wid >> 1;
    const int g = lane >> 2, tig = lane & 3;
    const int mtile = blockIdx.x;

    // ---- Prologue: A tile (h1, 128 rows x 64 halves, swizzled) ------------
    {
        const __half* xa = g_xs + (size_t)mtile * BM * KU;
#pragma unroll
        for (int i = 0; i < 4; i++) {
            int idx = tid + i * 256;          // 1024 16B chunks
            int row = idx >> 3, c = idx & 7;
            cp16(As_u + row * 128 + ((c ^ (row & 7)) << 4),
                 xa + (size_t)row * KU + c * 8);
        }
        cp_commit();
    }

    uint32_t aBase[4];
#pragma unroll
    for (int mi = 0; mi < 4; mi++)
        aBase[mi] = As_u + (wm * 64 + mi * 16 + (lane & 15)) * 128;
    const uint32_t amask = (lane & 7) << 4;
    const uint32_t asel  = lane >> 4;

    // per-thread fragment pointer base (ni = wn*4 + h*2 + j)
    const uint2* bp = g_e1f + (size_t)(wn * 4) * 32 + lane;

    float b1[8], b2[8];
    int   i1[8];
#pragma unroll
    for (int s = 0; s < 8; s++) { b1[s] = -3.402823466e38f; b2[s] = -3.402823466e38f; i1[s] = 0; }

    CP_WAIT(0);
    __syncthreads();

    // ---- Mainloop: 64 half-tiles (u = nt*2 + h), B double-buffered --------
    auto loadB = [&](int u, uint2 (&bf)[4][2]) {
        const int nt = u >> 1, h = u & 1;
        const uint2* p = bp + (size_t)nt * 2048 + (h * 2) * 32;
#pragma unroll
        for (int ks = 0; ks < 4; ks++)
#pragma unroll
            for (int j = 0; j < 2; j++)
                bf[ks][j] = __ldg(p + ks * 512 + j * 32);
    };
    auto computeH = [&](int u, uint2 (&bf)[4][2]) {
        const int nt = u >> 1, h = u & 1;
        float acc[4][2][4];
#pragma unroll
        for (int mi = 0; mi < 4; mi++)
#pragma unroll
            for (int j = 0; j < 2; j++)
#pragma unroll
                for (int r = 0; r < 4; r++) acc[mi][j][r] = 0.f;
#pragma unroll
        for (int ks = 0; ks < 4; ks++) {
            uint32_t a[4][4];
            const uint32_t aoff = (((uint32_t)(ks * 2) + asel) << 4) ^ amask;
#pragma unroll
            for (int mi = 0; mi < 4; mi++) ldsm4(a[mi], aBase[mi] + aoff);
#pragma unroll
            for (int mi = 0; mi < 4; mi++)
#pragma unroll
                for (int j = 0; j < 2; j++)
                    hmma(acc[mi][j],
                         a[mi],
                         reinterpret_cast<const uint32_t*>(&bf[ks][j]));
        }
        const int colb = nt * 128 + wn * 32 + h * 16 + tig * 2;
#pragma unroll
        for (int j = 0; j < 2; j++) {
            const int c0 = colb + j * 8;
            const float2 nh = *reinterpret_cast<const float2*>(&g_nhn[c0]);
#pragma unroll
            for (int mi = 0; mi < 4; mi++) {
                const int lo = mi * 2, hi = mi * 2 + 1;
                float s0 = acc[mi][j][0] + nh.x;
                float s1 = acc[mi][j][1] + nh.y;
                float s2 = acc[mi][j][2] + nh.x;
                float s3 = acc[mi][j][3] + nh.y;
                // branchless top-2 updates
                b2[lo] = fmaxf(b2[lo], fminf(b1[lo], s0));
                if (s0 > b1[lo]) { b1[lo] = s0; i1[lo] = c0; }
                b2[lo] = fmaxf(b2[lo], fminf(b1[lo], s1));
                if (s1 > b1[lo]) { b1[lo] = s1; i1[lo] = c0 + 1; }
                b2[hi] = fmaxf(b2[hi], fminf(b1[hi], s2));
                if (s2 > b1[hi]) { b1[hi] = s2; i1[hi] = c0; }
                b2[hi] = fmaxf(b2[hi], fminf(b1[hi], s3));
                if (s3 > b1[hi]) { b1[hi] = s3; i1[hi] = c0 + 1; }
            }
        }
    };

    uint2 bufA[4][2], bufB[4][2];
    loadB(0, bufA);
    for (int u = 0; u < 64; u += 2) {
        loadB(u + 1, bufB);
        computeH(u, bufA);
        if (u + 2 < 64) loadB(u + 2, bufA);
        computeH(u + 1, bufB);
    }

    // ---- quad reduce (top-2 over disjoint candidate sets) ------------------
#pragma unroll
    for (int s = 0; s < 8; s++) {
#pragma unroll
        for (int d = 1; d < 4; d <<= 1) {
            float ov1 = __shfl_xor_sync(0xffffffffu, b1[s], d);
            int   oi1 = __shfl_xor_sync(0xffffffffu, i1[s], d);
            float ov2 = __shfl_xor_sync(0xffffffffu, b2[s], d);
            if (ov1 > b1[s] || (ov1 == b1[s] && oi1 < i1[s])) {
                b2[s] = fmaxf(b1[s], ov2); b1[s] = ov1; i1[s] = oi1;
            } else {
                b2[s] = fmaxf(b2[s], ov1);
            }
        }
    }
    __syncthreads();   // A tile no longer needed; reuse smem for reduction
    float* rv1 = reinterpret_cast<float*>(smem);
    int*   ri1 = reinterpret_cast<int*>(smem + 2048);
    float* rv2 = reinterpret_cast<float*>(smem + 4096);
    if (tig == 0) {
#pragma unroll
        for (int s = 0; s < 8; s++) {
            int row = wm * 64 + (s >> 1) * 16 + g + (s & 1) * 8;
            rv1[row * 4 + wn] = b1[s];
            ri1[row * 4 + wn] = i1[s];
            rv2[row * 4 + wn] = b2[s];
        }
    }
    __syncthreads();

    if (tid < BM) {
        float B1 = rv1[tid * 4], B2 = rv2[tid * 4];
        int   I1 = ri1[tid * 4];
#pragma unroll
        for (int j = 1; j < 4; j++) {
            float a1 = rv1[tid * 4 + j], a2 = rv2[tid * 4 + j];
            int   ai = ri1[tid * 4 + j];
            if (a1 > B1 || (a1 == B1 && ai < I1)) {
                B2 = fmaxf(B1, a2); B1 = a1; I1 = ai;
            } else {
                B2 = fmaxf(B2, a1);
            }
        }
        const int grow = mtile * BM + tid;
        if (out_ind) out_ind[grow] = (float)I1;
        const float4* e4 = reinterpret_cast<const float4*>(embed + (size_t)I1 * DIM);
        float4* o4 = reinterpret_cast<float4*>(outq + (size_t)grow * DIM);
#pragma unroll
        for (int i = 0; i < DIM / 4; i++) o4[i] = e4[i];
        if (B1 - B2 < TAU) {
            int pos = atomicAdd(&g_cnt, 1);
            if (pos < CAP) {
                g_flag[pos] = grow;
                // fused compact: copy this row's (h1,h2) into g_cx
                const uint4* s4 = reinterpret_cast<const uint4*>(g_xs + (size_t)grow * KU);
                uint4* d4 = reinterpret_cast<uint4*>(g_cx + (size_t)pos * KU);
#pragma unroll
                for (int j = 0; j < 16; j++) d4[j] = s4[j];
            }
        }
    }
}

// ---------------------------------------------------------------------------
// Rescore: exact 3-term GEMM over flagged rows (8 codebook chunks x m-tiles).
// ---------------------------------------------------------------------------
#define RS_SMEM (32768 + 65536)

template<int TERMS>
__device__ __forceinline__ void compute_stage(
    float (&acc)[4][4][4], const uint32_t* aBase, uint32_t amask, uint32_t asel,
    uint32_t bst, const uint32_t* bOff, uint32_t bmask, uint32_t bsel)
{
#pragma unroll
    for (int ks = 0; ks < 4; ks++) {
        uint32_t b[4][2];
        const uint32_t boff = (((uint32_t)(ks * 2) + bsel) << 4) ^ bmask;
#pragma unroll
        for (int ni = 0; ni < 4; ni++) ldsm2(b[ni], bst + bOff[ni] + boff);
        const uint32_t aoff = (((uint32_t)(ks * 2) + asel) << 4) ^ amask;
#pragma unroll
        for (int t = 0; t < TERMS; t++) {
            uint32_t a[4][4];
#pragma unroll
            for (int mi = 0; mi < 4; mi++)
                ldsm4(a[mi], aBase[mi] + t * 16384 + aoff);
#pragma unroll
            for (int mi = 0; mi < 4; mi++)
#pragma unroll
                for (int ni = 0; ni < 4; ni++)
                    hmma(acc[mi][ni], a[mi], b[ni]);
        }
    }
}

__global__ __launch_bounds__(256, 2)
void vq_rescore2() {
    int cnt = g_cnt; if (cnt > CAP) cnt = CAP;
    extern __shared__ __align__(128) char smem[];
    const uint32_t As_u = smem_u32(smem);
    const uint32_t Bs_u = As_u + 32768;

    const int tid  = threadIdx.x;
    const int lane = tid & 31, wid = tid >> 5;
    const int wm = wid & 1, wn = wid >> 1;
    const int g = lane >> 2, tig = lane & 3;
    const int nchunk = blockIdx.x;

    uint32_t aBase[4];
#pragma unroll
    for (int mi = 0; mi < 4; mi++)
        aBase[mi] = As_u + (wm * 64 + mi * 16 + (lane & 15)) * 128;
    const uint32_t amask = (lane & 7) << 4;
    const uint32_t asel  = lane >> 4;
    uint32_t bOff[4];
#pragma unroll
    for (int ni = 0; ni < 4; ni++)
        bOff[ni] = (wn * 32 + ni * 8 + (lane & 7)) * 128;
    const uint32_t bmask = (lane & 7) << 4;
    const uint32_t bsel  = (lane >> 3) & 1;

    auto prefetchB = [&](int st, int slot) {
        const int nt = nchunk * 4 + (st >> 1), s = st & 1;
        const __half* src = g_es + (size_t)nt * BM * KU + s * DIM;
        const uint32_t dbase = Bs_u + slot * 16384;
#pragma unroll
        for (int i = 0; i < 4; i++) {
            int idx = tid + i * 256;
            int row = idx >> 3, c = idx & 7;
            cp16(dbase + row * 128 + ((c ^ (row & 7)) << 4),
                 src + (size_t)row * KU + c * 8);
        }
    };

    for (int mt = blockIdx.y; mt * BM < cnt; mt += gridDim.y) {
#pragma unroll
        for (int s = 0; s < 2; s++)
#pragma unroll
            for (int i = 0; i < 4; i++) {
                int idx = tid + i * 256;
                int row = idx >> 3, c = idx & 7;
                int ci = mt * BM + row; if (ci >= cnt) ci = cnt - 1;
                cp16(As_u + s * 16384 + row * 128 + ((c ^ (row & 7)) << 4),
                     g_cx + (size_t)ci * KU + s * DIM + c * 8);
            }
        prefetchB(0, 0); cp_commit();
        prefetchB(1, 1); cp_commit();
        prefetchB(2, 2); cp_commit();

        float bestv[8]; int bidxv[8];
#pragma unroll
        for (int s = 0; s < 8; s++) { bestv[s] = -3.402823466e38f; bidxv[s] = 0; }
        float acc[4][4][4];

        for (int si = 0; si < 8; si++) {
            const int cs = si & 1, ntl = si >> 1;
            CP_WAIT(2);
            __syncthreads();
            if (si < 5) prefetchB(si + 3, (si + 3) & 3);
            cp_commit();

            if (cs == 0) {
#pragma unroll
                for (int mi = 0; mi < 4; mi++)
#pragma unroll
                    for (int ni = 0; ni < 4; ni++)
#pragma unroll
                        for (int r = 0; r < 4; r++) acc[mi][ni][r] = 0.f;
            }
            const uint32_t bst = Bs_u + (si & 3) * 16384;
            if (cs == 0) compute_stage<2>(acc, aBase, amask, asel, bst, bOff, bmask, bsel);
            else         compute_stage<1>(acc, aBase, amask, asel, bst, bOff, bmask, bsel);

            if (cs == 1) {
                const int colb = (nchunk * 4 + ntl) * 128 + wn * 32 + tig * 2;
#pragma unroll
                for (int ni = 0; ni < 4; ni++) {
                    const int c0 = colb + ni * 8;
                    float2 nh = *reinterpret_cast<const float2*>(&g_nhn[c0]);
#pragma unroll
                    for (int mi = 0; mi < 4; mi++) {
                        float s0 = acc[mi][ni][0] + nh.x;
                        float s1 = acc[mi][ni][1] + nh.y;
                        float s2 = acc[mi][ni][2] + nh.x;
                        float s3 = acc[mi][ni][3] + nh.y;
                        const int lo = mi * 2, hi = mi * 2 + 1;
                        if (s0 > bestv[lo]) { bestv[lo] = s0; bidxv[lo] = c0; }
                        if (s1 > bestv[lo]) { bestv[lo] = s1; bidxv[lo] = c0 + 1; }
                        if (s2 > bestv[hi]) { bestv[hi] = s2; bidxv[hi] = c0; }
                        if (s3 > bestv[hi]) { bestv[hi] = s3; bidxv[hi] = c0 + 1; }
                    }
                }
            }
        }

#pragma unroll
        for (int s = 0; s < 8; s++) {
#pragma unroll
            for (int d = 1; d < 4; d <<= 1) {
                float ov = __shfl_xor_sync(0xffffffffu, bestv[s], d);
                int   oi = __shfl_xor_sync(0xffffffffu, bidxv[s], d);
                if (ov > bestv[s] || (ov == bestv[s] && oi < bidxv[s])) {
                    bestv[s] = ov; bidxv[s] = oi;
                }
            }
        }
        __syncthreads();
        float* redv = reinterpret_cast<float*>(smem + 32768);
        int*   redi = reinterpret_cast<int*>(smem + 32768 + 2048);
        if (tig == 0) {
#pragma unroll
            for (int s = 0; s < 8; s++) {
                int row = wm * 64 + (s >> 1) * 16 + g + (s & 1) * 8;
                redv[row * 4 + wn] = bestv[s];
                redi[row * 4 + wn] = bidxv[s];
            }
        }
        __syncthreads();
        if (tid < BM && mt * BM + tid < cnt) {
            float bv = redv[tid * 4];
            int   bi = redi[tid * 4];
#pragma unroll
            for (int j = 1; j < 4; j++) {
                float v  = redv[tid * 4 + j];
                int   ii = redi[tid * 4 + j];
                if (v > bv || (v == bv && ii < bi)) { bv = v; bi = ii; }
            }
            unsigned long long packed =
                ((unsigned long long)fkey(bv) << 32) | (unsigned)(4095 - bi);
            atomicMax(&g_best[mt * BM + tid], packed);
        }
        __syncthreads();
    }
}

// ---------------------------------------------------------------------------
// Writeback flagged rows from g_best
// ---------------------------------------------------------------------------
__global__ void writeback_kernel(const float* __restrict__ embed,
                                 float* __restrict__ outq,
                                 float* __restrict__ out_ind) {
    int n = g_cnt; if (n > CAP) n = CAP;
    for (int i = blockIdx.x * blockDim.x + threadIdx.x; i < n;
         i += gridDim.x * blockDim.x) {
        int row = g_flag[i];
        unsigned long long p = g_best[i];
        int idx = 4095 - (int)(p & 0xFFFu);
        if (out_ind) out_ind[row] = (float)idx;
        const float4* e4 = reinterpret_cast<const float4*>(embed + (size_t)idx * DIM);
        float4* o4 = reinterpret_cast<float4*>(outq + (size_t)row * DIM);
#pragma unroll
        for (int j = 0; j < DIM / 4; j++) o4[j] = e4[j];
    }
}

// Defensive tail fill (always launched to keep ncu launch index stable).
__global__ void fill_kernel(float* __restrict__ out, int start, int end) {
    int i = start + blockIdx.x * blockDim.x + threadIdx.x;
    if (i < end) out[i] = 0.f;
}

// ---------------------------------------------------------------------------
extern "C" void kernel_launch(void* const* d_in, const int* in_sizes, int n_in,
                              void* d_out, int out_size) {
    const float* x     = (const float*)d_in[0];
    const float* embed = (const float*)d_in[1];
    float* out = (float*)d_out;

    const int M = in_sizes[0] / DIM;  // 32768

    int nthr = M * 8 > CBK * 8 ? M * 8 : CBK * 8;
    // launch order arranged so vq_pass1 is the 6th launch (ncu -s 5 -c 1)
    split_kernel<<<(nthr + 255) / 256, 256>>>(x, embed, M);                 // 1
    hn_kernel<<<(CBK * 4 + 255) / 256, 256>>>(embed);                      // 2
    pack_kernel<<<(CBK * DIM / 4 + 255) / 256, 256>>>(embed);              // 3

    float* oind = (out_size >= M * DIM + M) ? (out + (size_t)M * DIM) : nullptr;
    int written = M * DIM + (oind ? M : 0);
    {
        int tail = out_size - written;
        int blocks = tail > 0 ? (tail + 255) / 256 : 1;
        fill_kernel<<<blocks, 256>>>(out, written, out_size);              // 4
    }
    init_best_kernel<<<CAP / 256, 256>>>();                                // 5

    cudaFuncSetAttribute(vq_pass1,
                         cudaFuncAttributeMaxDynamicSharedMemorySize, P1_SMEM);
    cudaFuncSetAttribute(vq_rescore2,
                         cudaFuncAttributeMaxDynamicSharedMemorySize, RS_SMEM);

    vq_pass1<<<M / BM, 256, P1_SMEM>>>(embed, out, oind);                  // 6
    vq_rescore2<<<dim3(8, 16), 256, RS_SMEM>>>();                          // 7
    writeback_kernel<<<32, 256>>>(embed, out, oind);                       // 8
}

// round 9
// speedup vs baseline: 1.3714x; 1.0509x over previous
#include <cuda_runtime.h>
#include <cuda_fp16.h>
#include <cstdint>
#include <cstddef>

#define DIM   64
#define CBK   4096
#define MAXM  32768
#define KU    128            // [h1|h2] fp16 slices per row
#define BM    128
#define TAU   0.15f
#define CAP   16384

// ---------------------------------------------------------------------------
// Device scratch (static)
// ---------------------------------------------------------------------------
__device__ float g_nhn[CBK];                                   // -0.5*||e||^2
__device__ __align__(256) __half g_xs[(size_t)MAXM * KU];      // x: h1|h2
__device__ __align__(256) __half g_es[(size_t)CBK * KU];       // e: h1|h2 (rescore)
__device__ __align__(256) uint4 g_e1f4[32768];                 // e1 frags, j-paired
__device__ int g_cnt;
__device__ int g_done[CAP / BM];
__device__ int g_flag[CAP];
__device__ __align__(256) __half g_cx[(size_t)CAP * KU];       // compacted flagged rows
__device__ unsigned long long g_best[CAP];

// ---------------------------------------------------------------------------
// PTX helpers
// ---------------------------------------------------------------------------
__device__ __forceinline__ uint32_t smem_u32(const void* p) {
    uint32_t a;
    asm("{ .reg .u64 t; cvta.to.shared.u64 t, %1; cvt.u32.u64 %0, t; }"
        : "=r"(a) : "l"(p));
    return a;
}
__device__ __forceinline__ void cp16(uint32_t dst, const void* src) {
    asm volatile("cp.async.cg.shared.global [%0], [%1], 16;" :: "r"(dst), "l"(src));
}
__device__ __forceinline__ void cp_commit() {
    asm volatile("cp.async.commit_group;");
}
#define CP_WAIT(n) asm volatile("cp.async.wait_group %0;" :: "n"(n) : "memory")
__device__ __forceinline__ void ldsm4(uint32_t* r, uint32_t addr) {
    asm volatile("ldmatrix.sync.aligned.m8n8.x4.shared.b16 {%0,%1,%2,%3}, [%4];"
                 : "=r"(r[0]), "=r"(r[1]), "=r"(r[2]), "=r"(r[3]) : "r"(addr));
}
__device__ __forceinline__ void ldsm2(uint32_t* r, uint32_t addr) {
    asm volatile("ldmatrix.sync.aligned.m8n8.x2.shared.b16 {%0,%1}, [%2];"
                 : "=r"(r[0]), "=r"(r[1]) : "r"(addr));
}
__device__ __forceinline__ void hmma(float* d, const uint32_t* a, const uint32_t* b) {
    asm volatile("mma.sync.aligned.m16n8k16.row.col.f32.f16.f16.f32 "
                 "{%0,%1,%2,%3}, {%4,%5,%6,%7}, {%8,%9}, {%0,%1,%2,%3};"
                 : "+f"(d[0]), "+f"(d[1]), "+f"(d[2]), "+f"(d[3])
                 : "r"(a[0]), "r"(a[1]), "r"(a[2]), "r"(a[3]),
                   "r"(b[0]), "r"(b[1]));
}
__device__ __forceinline__ uint32_t fkey(float f) {
    uint32_t u = __float_as_uint(f);
    return (u & 0x80000000u) ? ~u : (u | 0x80000000u);
}

// ---------------------------------------------------------------------------
// Split fp32 -> (h1,h2) fp16.  Exact 3-term score: h1e1 + h1e2 + h2e1.
// ---------------------------------------------------------------------------
__device__ __forceinline__ void split8(float4 lo, float4 hi, uint4* h) {
    float v[8] = {lo.x, lo.y, lo.z, lo.w, hi.x, hi.y, hi.z, hi.w};
    union U { unsigned short s[8]; uint4 u; } u1, u2;
#pragma unroll
    for (int k = 0; k < 8; k++) {
        float a = v[k];
        __half b1 = __float2half_rn(a);
        float r1 = a - __half2float(b1);
        __half b2 = __float2half_rn(r1);
        u1.s[k] = *reinterpret_cast<unsigned short*>(&b1);
        u2.s[k] = *reinterpret_cast<unsigned short*>(&b2);
    }
    h[0] = u1.u; h[1] = u2.u;
}

// ---------------------------------------------------------------------------
// Fused prologue: init state, split x, split e (+ -0.5||e||^2 via 8-lane
// shuffle reduce), pack e1 in j-paired mma fragment order.
// ---------------------------------------------------------------------------
__global__ void prep_kernel(const float* __restrict__ x,
                            const float* __restrict__ e, int M) {
    const int gid = blockIdx.x * blockDim.x + threadIdx.x;

    if (gid == 0) g_cnt = 0;
    if (gid < CAP) g_best[gid] = 0ULL;
    if (gid < CAP / BM) g_done[gid] = 0;

    // ---- e split + norm (gid < CBK*8 = 32768; warp-uniform branch) --------
    if (gid < CBK * 8) {
        int row = gid >> 3, c8 = gid & 7;
        const float4* p = reinterpret_cast<const float4*>(e + (size_t)row * DIM + c8 * 8);
        float4 lo = p[0], hi = p[1];
        uint4 h[2];
        split8(lo, hi, h);
        __half* dst = g_es + (size_t)row * KU + c8 * 8;
        *reinterpret_cast<uint4*>(dst)       = h[0];
        *reinterpret_cast<uint4*>(dst + DIM) = h[1];
        float s = lo.x * lo.x + lo.y * lo.y + lo.z * lo.z + lo.w * lo.w
                + hi.x * hi.x + hi.y * hi.y + hi.z * hi.z + hi.w * hi.w;
        s += __shfl_xor_sync(0xffffffffu, s, 1);
        s += __shfl_xor_sync(0xffffffffu, s, 2);
        s += __shfl_xor_sync(0xffffffffu, s, 4);
        if (c8 == 0) g_nhn[row] = -0.5f * s;
    }

    // ---- pack e1 fragments, j-paired uint4 (gid < 32768) -------------------
    // element idx = nt*1024 + ks*256 + nf2*32 + lane ; nf2 = wn*2 + h
    if (gid < 32768) {
        int lane = gid & 31;
        int nf2  = (gid >> 5) & 7;
        int ks   = (gid >> 8) & 3;
        int nt   = gid >> 10;
        int k0 = ks * 16 + (lane & 3) * 2;
        uint4 v;
#pragma unroll
        for (int j = 0; j < 2; j++) {
            int n = nt * 128 + (nf2 * 2 + j) * 8 + (lane >> 2);
            const float* er = e + (size_t)n * DIM;
            __half2 b0 = __floats2half2_rn(er[k0], er[k0 + 1]);
            __half2 b1 = __floats2half2_rn(er[k0 + 8], er[k0 + 9]);
            if (j == 0) { v.x = *reinterpret_cast<uint32_t*>(&b0);
                          v.y = *reinterpret_cast<uint32_t*>(&b1); }
            else        { v.z = *reinterpret_cast<uint32_t*>(&b0);
                          v.w = *reinterpret_cast<uint32_t*>(&b1); }
        }
        g_e1f4[gid] = v;
    }

    // ---- x split (gid < M*8) ----------------------------------------------
    if (gid < M * 8) {
        int row = gid >> 3, c8 = gid & 7;
        const float4* p = reinterpret_cast<const float4*>(x + (size_t)row * DIM + c8 * 8);
        uint4 h[2];
        split8(p[0], p[1], h);
        __half* dst = g_xs + (size_t)row * KU + c8 * 8;
        *reinterpret_cast<uint4*>(dst)       = h[0];
        *reinterpret_cast<uint4*>(dst + DIM) = h[1];
    }
}

// ---------------------------------------------------------------------------
// Pass 1: single-term fp16 GEMM (h1 . e1), B via LDG.128 of j-paired frags,
// A resident in SMEM, no syncthreads in the mainloop. Top-2 margin test;
// flagged rows compacted inline.
// ---------------------------------------------------------------------------
#define P1_SMEM 16384

__global__ __launch_bounds__(256, 2)
void vq_pass1(const float* __restrict__ embed,
              float* __restrict__ outq,
              float* __restrict__ out_ind) {
    extern __shared__ __align__(128) char smem[];
    const uint32_t As_u = smem_u32(smem);

    const int tid  = threadIdx.x;
    const int lane = tid & 31, wid = tid >> 5;
    const int wm = wid & 1, wn = wid >> 1;
    const int g = lane >> 2, tig = lane & 3;
    const int mtile = blockIdx.x;

    {   // A tile (h1, 128 rows x 64 halves, swizzled)
        const __half* xa = g_xs + (size_t)mtile * BM * KU;
#pragma unroll
        for (int i = 0; i < 4; i++) {
            int idx = tid + i * 256;
            int row = idx >> 3, c = idx & 7;
            cp16(As_u + row * 128 + ((c ^ (row & 7)) << 4),
                 xa + (size_t)row * KU + c * 8);
        }
        cp_commit();
    }

    uint32_t aBase[4];
#pragma unroll
    for (int mi = 0; mi < 4; mi++)
        aBase[mi] = As_u + (wm * 64 + mi * 16 + (lane & 15)) * 128;
    const uint32_t amask = (lane & 7) << 4;
    const uint32_t asel  = lane >> 4;

    const uint4* bp4 = g_e1f4 + (size_t)(wn * 2) * 32 + lane;

    float b1[8], b2[8];
    int   i1[8];
#pragma unroll
    for (int s = 0; s < 8; s++) { b1[s] = -3.402823466e38f; b2[s] = -3.402823466e38f; i1[s] = 0; }

    CP_WAIT(0);
    __syncthreads();

    auto loadB = [&](int u, uint4 (&bf)[4]) {
        const int nt = u >> 1, h = u & 1;
        const uint4* p = bp4 + (size_t)nt * 1024 + h * 32;
#pragma unroll
        for (int ks = 0; ks < 4; ks++) bf[ks] = __ldg(p + ks * 256);
    };
    auto computeH = [&](int u, uint4 (&bf)[4]) {
        const int nt = u >> 1, h = u & 1;
        float acc[4][2][4];
#pragma unroll
        for (int mi = 0; mi < 4; mi++)
#pragma unroll
            for (int j = 0; j < 2; j++)
#pragma unroll
                for (int r = 0; r < 4; r++) acc[mi][j][r] = 0.f;
#pragma unroll
        for (int ks = 0; ks < 4; ks++) {
            uint32_t a[4][4];
            const uint32_t aoff = (((uint32_t)(ks * 2) + asel) << 4) ^ amask;
#pragma unroll
            for (int mi = 0; mi < 4; mi++) ldsm4(a[mi], aBase[mi] + aoff);
            const uint32_t* bw = reinterpret_cast<const uint32_t*>(&bf[ks]);
#pragma unroll
            for (int mi = 0; mi < 4; mi++) {
                hmma(acc[mi][0], a[mi], bw);
                hmma(acc[mi][1], a[mi], bw + 2);
            }
        }
        const int colb = nt * 128 + wn * 32 + h * 16 + tig * 2;
#pragma unroll
        for (int j = 0; j < 2; j++) {
            const int c0 = colb + j * 8;
            const float2 nh = *reinterpret_cast<const float2*>(&g_nhn[c0]);
#pragma unroll
            for (int mi = 0; mi < 4; mi++) {
                const int lo = mi * 2, hi = mi * 2 + 1;
                float s0 = acc[mi][j][0] + nh.x;
                float s1 = acc[mi][j][1] + nh.y;
                float s2 = acc[mi][j][2] + nh.x;
                float s3 = acc[mi][j][3] + nh.y;
                b2[lo] = fmaxf(b2[lo], fminf(b1[lo], s0));
                if (s0 > b1[lo]) { b1[lo] = s0; i1[lo] = c0; }
                b2[lo] = fmaxf(b2[lo], fminf(b1[lo], s1));
                if (s1 > b1[lo]) { b1[lo] = s1; i1[lo] = c0 + 1; }
                b2[hi] = fmaxf(b2[hi], fminf(b1[hi], s2));
                if (s2 > b1[hi]) { b1[hi] = s2; i1[hi] = c0; }
                b2[hi] = fmaxf(b2[hi], fminf(b1[hi], s3));
                if (s3 > b1[hi]) { b1[hi] = s3; i1[hi] = c0 + 1; }
            }
        }
    };

    uint4 bufA[4], bufB[4];
    loadB(0, bufA);
    for (int u = 0; u < 64; u += 2) {
        loadB(u + 1, bufB);
        computeH(u, bufA);
        if (u + 2 < 64) loadB(u + 2, bufA);
        computeH(u + 1, bufB);
    }

    // quad reduce (top-2 over disjoint candidate sets)
#pragma unroll
    for (int s = 0; s < 8; s++) {
#pragma unroll
        for (int d = 1; d < 4; d <<= 1) {
            float ov1 = __shfl_xor_sync(0xffffffffu, b1[s], d);
            int   oi1 = __shfl_xor_sync(0xffffffffu, i1[s], d);
            float ov2 = __shfl_xor_sync(0xffffffffu, b2[s], d);
            if (ov1 > b1[s] || (ov1 == b1[s] && oi1 < i1[s])) {
                b2[s] = fmaxf(b1[s], ov2); b1[s] = ov1; i1[s] = oi1;
            } else {
                b2[s] = fmaxf(b2[s], ov1);
            }
        }
    }
    __syncthreads();
    float* rv1 = reinterpret_cast<float*>(smem);
    int*   ri1 = reinterpret_cast<int*>(smem + 2048);
    float* rv2 = reinterpret_cast<float*>(smem + 4096);
    if (tig == 0) {
#pragma unroll
        for (int s = 0; s < 8; s++) {
            int row = wm * 64 + (s >> 1) * 16 + g + (s & 1) * 8;
            rv1[row * 4 + wn] = b1[s];
            ri1[row * 4 + wn] = i1[s];
            rv2[row * 4 + wn] = b2[s];
        }
    }
    __syncthreads();

    if (tid < BM) {
        float B1 = rv1[tid * 4], B2 = rv2[tid * 4];
        int   I1 = ri1[tid * 4];
#pragma unroll
        for (int j = 1; j < 4; j++) {
            float a1 = rv1[tid * 4 + j], a2 = rv2[tid * 4 + j];
            int   ai = ri1[tid * 4 + j];
            if (a1 > B1 || (a1 == B1 && ai < I1)) {
                B2 = fmaxf(B1, a2); B1 = a1; I1 = ai;
            } else {
                B2 = fmaxf(B2, a1);
            }
        }
        const int grow = mtile * BM + tid;
        if (out_ind) out_ind[grow] = (float)I1;
        const float4* e4 = reinterpret_cast<const float4*>(embed + (size_t)I1 * DIM);
        float4* o4 = reinterpret_cast<float4*>(outq + (size_t)grow * DIM);
#pragma unroll
        for (int i = 0; i < DIM / 4; i++) o4[i] = e4[i];
        if (B1 - B2 < TAU) {
            int pos = atomicAdd(&g_cnt, 1);
            if (pos < CAP) {
                g_flag[pos] = grow;
                const uint4* s4 = reinterpret_cast<const uint4*>(g_xs + (size_t)grow * KU);
                uint4* d4 = reinterpret_cast<uint4*>(g_cx + (size_t)pos * KU);
#pragma unroll
                for (int j = 0; j < 16; j++) d4[j] = s4[j];
            }
        }
    }
}

// ---------------------------------------------------------------------------
// Rescore (exact 3-term) over flagged rows, 8 codebook chunks x m-tiles,
// with fused writeback by the last-finishing chunk block per m-tile.
// ---------------------------------------------------------------------------
#define RS_SMEM (32768 + 65536)

template<int TERMS>
__device__ __forceinline__ void compute_stage(
    float (&acc)[4][4][4], const uint32_t* aBase, uint32_t amask, uint32_t asel,
    uint32_t bst, const uint32_t* bOff, uint32_t bmask, uint32_t bsel)
{
#pragma unroll
    for (int ks = 0; ks < 4; ks++) {
        uint32_t b[4][2];
        const uint32_t boff = (((uint32_t)(ks * 2) + bsel) << 4) ^ bmask;
#pragma unroll
        for (int ni = 0; ni < 4; ni++) ldsm2(b[ni], bst + bOff[ni] + boff);
        const uint32_t aoff = (((uint32_t)(ks * 2) + asel) << 4) ^ amask;
#pragma unroll
        for (int t = 0; t < TERMS; t++) {
            uint32_t a[4][4];
#pragma unroll
            for (int mi = 0; mi < 4; mi++)
                ldsm4(a[mi], aBase[mi] + t * 16384 + aoff);
#pragma unroll
            for (int mi = 0; mi < 4; mi++)
#pragma unroll
                for (int ni = 0; ni < 4; ni++)
                    hmma(acc[mi][ni], a[mi], b[ni]);
        }
    }
}

__global__ __launch_bounds__(256, 2)
void vq_rescore(const float* __restrict__ embed,
                float* __restrict__ outq,
                float* __restrict__ out_ind) {
    int cnt = g_cnt; if (cnt > CAP) cnt = CAP;
    extern __shared__ __align__(128) char smem[];
    __shared__ int s_last;
    const uint32_t As_u = smem_u32(smem);
    const uint32_t Bs_u = As_u + 32768;

    const int tid  = threadIdx.x;
    const int lane = tid & 31, wid = tid >> 5;
    const int wm = wid & 1, wn = wid >> 1;
    const int g = lane >> 2, tig = lane & 3;
    const int nchunk = blockIdx.x;

    uint32_t aBase[4];
#pragma unroll
    for (int mi = 0; mi < 4; mi++)
        aBase[mi] = As_u + (wm * 64 + mi * 16 + (lane & 15)) * 128;
    const uint32_t amask = (lane & 7) << 4;
    const uint32_t asel  = lane >> 4;
    uint32_t bOff[4];
#pragma unroll
    for (int ni = 0; ni < 4; ni++)
        bOff[ni] = (wn * 32 + ni * 8 + (lane & 7)) * 128;
    const uint32_t bmask = (lane & 7) << 4;
    const uint32_t bsel  = (lane >> 3) & 1;

    auto prefetchB = [&](int st, int slot) {
        const int nt = nchunk * 4 + (st >> 1), s = st & 1;
        const __half* src = g_es + (size_t)nt * BM * KU + s * DIM;
        const uint32_t dbase = Bs_u + slot * 16384;
#pragma unroll
        for (int i = 0; i < 4; i++) {
            int idx = tid + i * 256;
            int row = idx >> 3, c = idx & 7;
            cp16(dbase + row * 128 + ((c ^ (row & 7)) << 4),
                 src + (size_t)row * KU + c * 8);
        }
    };

    for (int mt = blockIdx.y; mt * BM < cnt; mt += gridDim.y) {
#pragma unroll
        for (int s = 0; s < 2; s++)
#pragma unroll
            for (int i = 0; i < 4; i++) {
                int idx = tid + i * 256;
                int row = idx >> 3, c = idx & 7;
                int ci = mt * BM + row; if (ci >= cnt) ci = cnt - 1;
                cp16(As_u + s * 16384 + row * 128 + ((c ^ (row & 7)) << 4),
                     g_cx + (size_t)ci * KU + s * DIM + c * 8);
            }
        prefetchB(0, 0); cp_commit();
        prefetchB(1, 1); cp_commit();
        prefetchB(2, 2); cp_commit();

        float bestv[8]; int bidxv[8];
#pragma unroll
        for (int s = 0; s < 8; s++) { bestv[s] = -3.402823466e38f; bidxv[s] = 0; }
        float acc[4][4][4];

        for (int si = 0; si < 8; si++) {
            const int cs = si & 1, ntl = si >> 1;
            CP_WAIT(2);
            __syncthreads();
            if (si < 5) prefetchB(si + 3, (si + 3) & 3);
            cp_commit();

            if (cs == 0) {
#pragma unroll
                for (int mi = 0; mi < 4; mi++)
#pragma unroll
                    for (int ni = 0; ni < 4; ni++)
#pragma unroll
                        for (int r = 0; r < 4; r++) acc[mi][ni][r] = 0.f;
            }
            const uint32_t bst = Bs_u + (si & 3) * 16384;
            if (cs == 0) compute_stage<2>(acc, aBase, amask, asel, bst, bOff, bmask, bsel);
            else         compute_stage<1>(acc, aBase, amask, asel, bst, bOff, bmask, bsel);

            if (cs == 1) {
                const int colb = (nchunk * 4 + ntl) * 128 + wn * 32 + tig * 2;
#pragma unroll
                for (int ni = 0; ni < 4; ni++) {
                    const int c0 = colb + ni * 8;
                    float2 nh = *reinterpret_cast<const float2*>(&g_nhn[c0]);
#pragma unroll
                    for (int mi = 0; mi < 4; mi++) {
                        float s0 = acc[mi][ni][0] + nh.x;
                        float s1 = acc[mi][ni][1] + nh.y;
                        float s2 = acc[mi][ni][2] + nh.x;
                        float s3 = acc[mi][ni][3] + nh.y;
                        const int lo = mi * 2, hi = mi * 2 + 1;
                        if (s0 > bestv[lo]) { bestv[lo] = s0; bidxv[lo] = c0; }
                        if (s1 > bestv[lo]) { bestv[lo] = s1; bidxv[lo] = c0 + 1; }
                        if (s2 > bestv[hi]) { bestv[hi] = s2; bidxv[hi] = c0; }
                        if (s3 > bestv[hi]) { bestv[hi] = s3; bidxv[hi] = c0 + 1; }
                    }
                }
            }
        }

#pragma unroll
        for (int s = 0; s < 8; s++) {
#pragma unroll
            for (int d = 1; d < 4; d <<= 1) {
                float ov = __shfl_xor_sync(0xffffffffu, bestv[s], d);
                int   oi = __shfl_xor_sync(0xffffffffu, bidxv[s], d);
                if (ov > bestv[s] || (ov == bestv[s] && oi < bidxv[s])) {
                    bestv[s] = ov; bidxv[s] = oi;
                }
            }
        }
        __syncthreads();
        float* redv = reinterpret_cast<float*>(smem + 32768);
        int*   redi = reinterpret_cast<int*>(smem + 32768 + 2048);
        if (tig == 0) {
#pragma unroll
            for (int s = 0; s < 8; s++) {
                int row = wm * 64 + (s >> 1) * 16 + g + (s & 1) * 8;
                redv[row * 4 + wn] = bestv[s];
                redi[row * 4 + wn] = bidxv[s];
            }
        }
        __syncthreads();
        if (tid < BM && mt * BM + tid < cnt) {
            float bv = redv[tid * 4];
            int   bi = redi[tid * 4];
#pragma unroll
            for (int j = 1; j < 4; j++) {
                float v  = redv[tid * 4 + j];
                int   ii = redi[tid * 4 + j];
                if (v > bv || (v == bv && ii < bi)) { bv = v; bi = ii; }
            }
            unsigned long long packed =
                ((unsigned long long)fkey(bv) << 32) | (unsigned)(4095 - bi);
            atomicMax(&g_best[mt * BM + tid], packed);
        }
        __syncthreads();

        // ---- last-arriving chunk for this m-tile performs writeback -------
        if (tid == 0) {
            __threadfence();
            int r = atomicAdd(&g_done[mt], 1);
            s_last = (r == 7) ? 1 : 0;
        }
        __syncthreads();
        if (s_last) {
            __threadfence();
            int li = mt * BM + (tid >> 1);
            if (li < cnt) {
                int row = g_flag[li];
                unsigned long long p = g_best[li];
                int idx = 4095 - (int)(p & 0xFFFu);
                int half = tid & 1;
                if (half == 0 && out_ind) out_ind[row] = (float)idx;
                const float4* e4 =
                    reinterpret_cast<const float4*>(embed + (size_t)idx * DIM) + half * 8;
                float4* o4 =
                    reinterpret_cast<float4*>(outq + (size_t)row * DIM) + half * 8;
#pragma unroll
                for (int j = 0; j < 8; j++) o4[j] = e4[j];
            }
        }
        __syncthreads();
    }
}

// Defensive tail fill (launched only when a tail exists).
__global__ void fill_kernel(float* __restrict__ out, int start, int end) {
    int i = start + blockIdx.x * blockDim.x + threadIdx.x;
    if (i < end) out[i] = 0.f;
}

// ---------------------------------------------------------------------------
extern "C" void kernel_launch(void* const* d_in, const int* in_sizes, int n_in,
                              void* d_out, int out_size) {
    const float* x     = (const float*)d_in[0];
    const float* embed = (const float*)d_in[1];
    float* out = (float*)d_out;

    const int M = in_sizes[0] / DIM;  // 32768

    prep_kernel<<<(M * 8 + 255) / 256, 256>>>(x, embed, M);

    cudaFuncSetAttribute(vq_pass1,
                         cudaFuncAttributeMaxDynamicSharedMemorySize, P1_SMEM);
    cudaFuncSetAttribute(vq_rescore,
                         cudaFuncAttributeMaxDynamicSharedMemorySize, RS_SMEM);

    float* oind = (out_size >= M * DIM + M) ? (out + (size_t)M * DIM) : nullptr;
    vq_pass1<<<M / BM, 256, P1_SMEM>>>(embed, out, oind);
    vq_rescore<<<dim3(8, 16), 256, RS_SMEM>>>(embed, out, oind);

    int written = M * DIM + (oind ? M : 0);
    if (out_size > written) {
        int tail = out_size - written;
        fill_kernel<<<(tail + 255) / 256, 256>>>(out, written, out_size);
    }
}